// round 2
// baseline (speedup 1.0000x reference)
#include <cuda_runtime.h>
#include <cstdint>

#define MAXN 50000
#define MAXE 1600000

// Scratch (device globals — no allocation allowed). 16B-aligned for float4/red.v4.
__device__ __align__(16) float g_h1[MAXN * 64];    // layer1 pre-agg features [N,2,32]
__device__ __align__(16) float g_es1[MAXN * 2];
__device__ __align__(16) float g_ed1[MAXN * 2];
__device__ __align__(16) float g_acc1[MAXN * 64];  // layer1 aggregate -> relu'd h2-input
__device__ __align__(16) float g_den1[MAXN * 2];
__device__ __align__(16) float g_h2[MAXN * 32];    // layer2 pre-agg features
__device__ __align__(16) float g_es2[MAXN];
__device__ __align__(16) float g_ed2[MAXN];
__device__ __align__(16) float g_den2[MAXN];

static __device__ __forceinline__ void red_add_v4(float* p, float a, float b, float c, float d) {
    asm volatile("red.global.add.v4.f32 [%0], {%1,%2,%3,%4};"
                 :: "l"(p), "f"(a), "f"(b), "f"(c), "f"(d) : "memory");
}

static __device__ __forceinline__ float lrelu(float v) {
    return v > 0.0f ? v : 0.2f * v;
}

// ---------------------------------------------------------------------------
// Zero all accumulators + output
// ---------------------------------------------------------------------------
__global__ void zero_kernel(float* __restrict__ out, int n) {
    int i = blockIdx.x * blockDim.x + threadIdx.x;
    int n64 = n * 64, n66 = n * 66, n67 = n * 67, n99 = n * 99;
    if (i < n64)       g_acc1[i] = 0.0f;
    else if (i < n66)  g_den1[i - n64] = 0.0f;
    else if (i < n67)  g_den2[i - n66] = 0.0f;
    else if (i < n99)  out[i - n67] = 0.0f;
}

// ---------------------------------------------------------------------------
// GEMM1: h1[N,64] = x[N,128] @ W1[128,64]   (BM=64, BN=64, BK=16, 4x4 tiles)
// ---------------------------------------------------------------------------
__global__ void gemm1_kernel(const float* __restrict__ x, const float* __restrict__ W, int n) {
    __shared__ __align__(16) float As[16][64];
    __shared__ __align__(16) float Bs[16][64];
    const int t = threadIdx.x;
    const int row0 = blockIdx.x * 64;
    const int tr = t >> 4, tc = t & 15;        // 16x16 thread grid, 4x4 each
    const int lm = t & 63, lk = (t >> 6) << 2; // A-load mapping
    const int bk = t >> 4, bn = (t & 15) << 2; // B-load mapping
    float acc[4][4] = {};
    const int r = row0 + lm;

    for (int kt = 0; kt < 128; kt += 16) {
        float4 av = make_float4(0.f, 0.f, 0.f, 0.f);
        if (r < n) av = *reinterpret_cast<const float4*>(x + (size_t)r * 128 + kt + lk);
        As[lk + 0][lm] = av.x; As[lk + 1][lm] = av.y;
        As[lk + 2][lm] = av.z; As[lk + 3][lm] = av.w;
        *reinterpret_cast<float4*>(&Bs[bk][bn]) =
            *reinterpret_cast<const float4*>(W + (size_t)(kt + bk) * 64 + bn);
        __syncthreads();
        #pragma unroll
        for (int kk = 0; kk < 16; kk++) {
            float4 a4 = *reinterpret_cast<const float4*>(&As[kk][tr << 2]);
            float4 b4 = *reinterpret_cast<const float4*>(&Bs[kk][tc << 2]);
            float aa[4] = {a4.x, a4.y, a4.z, a4.w};
            float bb[4] = {b4.x, b4.y, b4.z, b4.w};
            #pragma unroll
            for (int i = 0; i < 4; i++)
                #pragma unroll
                for (int j = 0; j < 4; j++)
                    acc[i][j] = fmaf(aa[i], bb[j], acc[i][j]);
        }
        __syncthreads();
    }
    #pragma unroll
    for (int i = 0; i < 4; i++) {
        int rr = row0 + (tr << 2) + i;
        if (rr < n)
            *reinterpret_cast<float4*>(g_h1 + (size_t)rr * 64 + (tc << 2)) =
                make_float4(acc[i][0], acc[i][1], acc[i][2], acc[i][3]);
    }
}

// ---------------------------------------------------------------------------
// Per-node attention scores, layer1 (H=2, C=32): one warp per node
// ---------------------------------------------------------------------------
__global__ void scores1_kernel(const float* __restrict__ a_src, const float* __restrict__ a_dst, int n) {
    int gid = blockIdx.x * blockDim.x + threadIdx.x;
    int node = gid >> 5, lane = gid & 31;
    if (node >= n) return;
    float h0 = g_h1[(size_t)node * 64 + lane];
    float h1 = g_h1[(size_t)node * 64 + 32 + lane];
    float s0 = h0 * a_src[lane],      s1 = h1 * a_src[32 + lane];
    float d0 = h0 * a_dst[lane],      d1 = h1 * a_dst[32 + lane];
    #pragma unroll
    for (int off = 16; off; off >>= 1) {
        s0 += __shfl_xor_sync(0xffffffffu, s0, off);
        s1 += __shfl_xor_sync(0xffffffffu, s1, off);
        d0 += __shfl_xor_sync(0xffffffffu, d0, off);
        d1 += __shfl_xor_sync(0xffffffffu, d1, off);
    }
    if (lane == 0) {
        g_es1[node * 2] = s0; g_es1[node * 2 + 1] = s1;
        g_ed1[node * 2] = d0; g_ed1[node * 2 + 1] = d1;
    }
}

// ---------------------------------------------------------------------------
// Edge pass, layer1: 16 lanes per edge. p=exp(lrelu(es[src]+ed[dst])) (no max-shift),
// accumulate denom[dst] and p*h1[src] into acc1[dst].
// ---------------------------------------------------------------------------
__global__ void edge1_kernel(const int* __restrict__ ei, int E, int nTot) {
    int gid = blockIdx.x * blockDim.x + threadIdx.x;
    int e = gid >> 4;
    if (e >= nTot) return;
    int lg = gid & 15;
    int s, d;
    if (e < E) { s = ei[e]; d = ei[E + e]; }
    else       { s = d = e - E; }
    float2 es = *reinterpret_cast<const float2*>(g_es1 + 2 * s);
    float2 ed = *reinterpret_cast<const float2*>(g_ed1 + 2 * d);
    float p0 = __expf(lrelu(es.x + ed.x));
    float p1 = __expf(lrelu(es.y + ed.y));
    if (lg == 0) {
        atomicAdd(g_den1 + 2 * d,     p0);
        atomicAdd(g_den1 + 2 * d + 1, p1);
    }
    float4 h = *reinterpret_cast<const float4*>(g_h1 + (size_t)s * 64 + lg * 4);
    float p = (lg < 8) ? p0 : p1;
    red_add_v4(g_acc1 + (size_t)d * 64 + lg * 4, p * h.x, p * h.y, p * h.z, p * h.w);
}

// ---------------------------------------------------------------------------
// Finalize layer1: acc1 = relu(acc1/(den1+eps) + b1)   (in place)
// ---------------------------------------------------------------------------
__global__ void finalize1_kernel(const float* __restrict__ b1, int n) {
    int i = blockIdx.x * blockDim.x + threadIdx.x;
    if (i >= n * 64) return;
    int node = i >> 6, j = i & 63;
    float v = g_acc1[i] / (g_den1[node * 2 + (j >> 5)] + 1e-16f) + b1[j];
    g_acc1[i] = v > 0.0f ? v : 0.0f;
}

// ---------------------------------------------------------------------------
// GEMM2: h2[N,32] = acc1[N,64] @ W2[64,32]  (one warp per row, W2 in smem)
// ---------------------------------------------------------------------------
__global__ void gemm2_kernel(const float* __restrict__ W2, int n) {
    __shared__ float W2s[64 * 32];
    for (int i = threadIdx.x; i < 64 * 32; i += blockDim.x) W2s[i] = W2[i];
    __syncthreads();
    int gid = blockIdx.x * blockDim.x + threadIdx.x;
    int row = gid >> 5, lane = gid & 31;
    if (row >= n) return;
    const float* a = g_acc1 + (size_t)row * 64;
    float sum = 0.0f;
    #pragma unroll
    for (int k = 0; k < 64; k++) sum = fmaf(a[k], W2s[k * 32 + lane], sum);
    g_h2[(size_t)row * 32 + lane] = sum;
}

// ---------------------------------------------------------------------------
// Per-node scores, layer2 (H=1, C=32)
// ---------------------------------------------------------------------------
__global__ void scores2_kernel(const float* __restrict__ a_src, const float* __restrict__ a_dst, int n) {
    int gid = blockIdx.x * blockDim.x + threadIdx.x;
    int node = gid >> 5, lane = gid & 31;
    if (node >= n) return;
    float h = g_h2[(size_t)node * 32 + lane];
    float s = h * a_src[lane];
    float d = h * a_dst[lane];
    #pragma unroll
    for (int off = 16; off; off >>= 1) {
        s += __shfl_xor_sync(0xffffffffu, s, off);
        d += __shfl_xor_sync(0xffffffffu, d, off);
    }
    if (lane == 0) { g_es2[node] = s; g_ed2[node] = d; }
}

// ---------------------------------------------------------------------------
// Edge pass, layer2: 8 lanes per edge, accumulate directly into d_out
// ---------------------------------------------------------------------------
__global__ void edge2_kernel(const int* __restrict__ ei, int E, int nTot,
                             float* __restrict__ out) {
    int gid = blockIdx.x * blockDim.x + threadIdx.x;
    int e = gid >> 3;
    if (e >= nTot) return;
    int lg = gid & 7;
    int s, d;
    if (e < E) { s = ei[e]; d = ei[E + e]; }
    else       { s = d = e - E; }
    float p = __expf(lrelu(g_es2[s] + g_ed2[d]));
    if (lg == 0) atomicAdd(g_den2 + d, p);
    float4 h = *reinterpret_cast<const float4*>(g_h2 + (size_t)s * 32 + lg * 4);
    red_add_v4(out + (size_t)d * 32 + lg * 4, p * h.x, p * h.y, p * h.z, p * h.w);
}

// ---------------------------------------------------------------------------
// Finalize layer2: out = out/(den2+eps) + b2  (in place)
// ---------------------------------------------------------------------------
__global__ void finalize2_kernel(const float* __restrict__ b2, int n, float* __restrict__ out) {
    int i = blockIdx.x * blockDim.x + threadIdx.x;
    if (i >= n * 32) return;
    int node = i >> 5, c = i & 31;
    out[i] = out[i] / (g_den2[node] + 1e-16f) + b2[c];
}

// ---------------------------------------------------------------------------
extern "C" void kernel_launch(void* const* d_in, const int* in_sizes, int n_in,
                              void* d_out, int out_size) {
    const float* x      = (const float*)d_in[0];
    const int*   ei     = (const int*)d_in[1];
    const float* W1     = (const float*)d_in[2];
    const float* a_src1 = (const float*)d_in[3];
    const float* a_dst1 = (const float*)d_in[4];
    const float* b1     = (const float*)d_in[5];
    const float* W2     = (const float*)d_in[6];
    const float* a_src2 = (const float*)d_in[7];
    const float* a_dst2 = (const float*)d_in[8];
    const float* b2     = (const float*)d_in[9];
    float* out = (float*)d_out;

    const int n    = in_sizes[0] / 128;   // 50000
    const int E    = in_sizes[1] / 2;     // 1600000
    const int nTot = E + n;               // edges + self loops

    zero_kernel<<<(99 * n + 255) / 256, 256>>>(out, n);
    gemm1_kernel<<<(n + 63) / 64, 256>>>(x, W1, n);
    scores1_kernel<<<(n * 32 + 255) / 256, 256>>>(a_src1, a_dst1, n);
    edge1_kernel<<<(int)(((long long)nTot * 16 + 255) / 256), 256>>>(ei, E, nTot);
    finalize1_kernel<<<(n * 64 + 255) / 256, 256>>>(b1, n);
    gemm2_kernel<<<(n * 32 + 255) / 256, 256>>>(W2, n);
    scores2_kernel<<<(n * 32 + 255) / 256, 256>>>(a_src2, a_dst2, n);
    edge2_kernel<<<(int)(((long long)nTot * 8 + 255) / 256), 256>>>(ei, E, nTot, out);
    finalize2_kernel<<<(n * 32 + 255) / 256, 256>>>(b2, n, out);
}